// round 15
// baseline (speedup 1.0000x reference)
#include <cuda_runtime.h>
#include <cuda_fp16.h>
#include <cstdint>
#include <math.h>

#define BS 8
#define LQ 1000
#define DD 256
#define NH 8
#define NL 4
#define NP 4
#define CC 32
#define LV 8500   // 80*80 + 40*40 + 20*20 + 10*10

// ---------------- scratch (static device globals; no dynamic alloc) --------
__device__ __align__(16) __half g_vph [(size_t)BS * LV * DD];   // projected value fp16
__device__ __align__(16) float  g_offattn[(size_t)BS * LQ * 384]; // off(256) | attn(128)
__device__ __align__(16) __half g_tmph[(size_t)BS * LQ * DD];   // aggregated fp16
__device__ __align__(16) __half g_wvT [DD * DD];                // [N][K] fp16
__device__ __align__(16) __half g_wqT [384 * DD];               // [w_off^T ; w_attn^T]
__device__ __align__(16) float  g_bq  [384];                    // b_off | b_attn
__device__ __align__(16) __half g_woT [DD * DD];

// ======================= helpers ===========================================
__device__ __forceinline__ void cpasync16(uint32_t dst, const void* src) {
    asm volatile("cp.async.cg.shared.global [%0], [%1], 16;" :: "r"(dst), "l"(src));
}
__device__ __forceinline__ void cp_commit() { asm volatile("cp.async.commit_group;"); }

template <int N>
__device__ __forceinline__ void cp_wait() {
    asm volatile("cp.async.wait_group %0;" :: "n"(N));
}

__device__ __forceinline__ uint32_t ld2cvt(const float* p) {
    float2 f = *(const float2*)p;
    __half2 h = __floats2half2_rn(f.x, f.y);
    return *(uint32_t*)&h;
}

__device__ __forceinline__ void mma16816(float* a4, uint32_t a0, uint32_t a1,
                                         uint32_t a2, uint32_t a3,
                                         uint32_t b0, uint32_t b1) {
    asm volatile(
        "mma.sync.aligned.m16n8k16.row.col.f32.f16.f16.f32 "
        "{%0,%1,%2,%3}, {%4,%5,%6,%7}, {%8,%9}, {%0,%1,%2,%3};"
        : "+f"(a4[0]), "+f"(a4[1]), "+f"(a4[2]), "+f"(a4[3])
        : "r"(a0), "r"(a1), "r"(a2), "r"(a3), "r"(b0), "r"(b1));
}

// ====== fp32-A tensor-core GEMM body (K=256, tile 128x128, BK=32) ==========
#define LDA 36
#define LDB 40
#define STG_A (128 * LDA)
#define STG_B (128 * LDB)
#define SMEM_A_BYTES (3 * STG_A * 4)                   // 55296
#define SMEM_GEMM    (SMEM_A_BYTES + 3 * STG_B * 2)    // 86016

// K4: full-K prefetch, 8 stages of (A fp16 + B fp16)
#define SMEM_K4_A (8 * STG_B * 2)                      // 81920
#define SMEM_K4   (2 * SMEM_K4_A)                      // 163840

__device__ __forceinline__
void gemm_body(const float* __restrict__ A, const __half* __restrict__ BT,
               const float* __restrict__ bias, float* __restrict__ Cf,
               __half* __restrict__ Ch, int M, int N, int brow, int ncol)
{
    extern __shared__ __align__(16) char smem[];
    float*  As = (float*)smem;
    __half* Bs = (__half*)(smem + SMEM_A_BYTES);

    const int tid  = threadIdx.x;
    const int wid  = tid >> 5;
    const int lane = tid & 31;
    const int wm   = (wid & 3) * 32;
    const int wn   = (wid >> 2) * 64;
    const int grp  = lane >> 2;
    const int tig  = lane & 3;

    float acc[2][8][4];
#pragma unroll
    for (int i = 0; i < 2; i++)
#pragma unroll
        for (int j = 0; j < 8; j++)
#pragma unroll
            for (int r = 0; r < 4; r++) acc[i][j][r] = 0.f;

    auto load = [&](int kb, int stg) {
#pragma unroll
        for (int t = 0; t < 4; t++) {
            const int lin = tid + t * 256;
            const int row = lin >> 3;
            const int c   = lin & 7;
            const float* sa = A + (size_t)min(brow + row, M - 1) * 256 + kb + c * 4;
            cpasync16((uint32_t)__cvta_generic_to_shared(&As[stg * STG_A + row * LDA + c * 4]), sa);
        }
#pragma unroll
        for (int t = 0; t < 2; t++) {
            const int lin = tid + t * 256;
            const int row = lin >> 2;
            const int c   = lin & 3;
            const __half* sb = BT + (size_t)(ncol + row) * 256 + kb + c * 8;
            cpasync16((uint32_t)__cvta_generic_to_shared(&Bs[stg * STG_B + row * LDB + c * 8]), sb);
        }
        cp_commit();
    };

    load(0, 0);
    load(32, 1);

    for (int it = 0; it < 8; it++) {
        const int buf = it % 3;
        if (it + 2 < 8) load((it + 2) * 32, (it + 2) % 3);
        if (it < 6)       asm volatile("cp.async.wait_group 2;");
        else if (it == 6) asm volatile("cp.async.wait_group 1;");
        else              asm volatile("cp.async.wait_group 0;");
        __syncthreads();

        const float*  Ab = As + buf * STG_A;
        const __half* Bb = Bs + buf * STG_B;

#pragma unroll
        for (int ks = 0; ks < 2; ks++) {
            const int kh = ks * 16;
            uint32_t af[2][4];
#pragma unroll
            for (int mi = 0; mi < 2; mi++) {
                const int r0 = wm + mi * 16 + grp;
                af[mi][0] = ld2cvt(Ab + (r0    ) * LDA + kh + tig * 2);
                af[mi][1] = ld2cvt(Ab + (r0 + 8) * LDA + kh + tig * 2);
                af[mi][2] = ld2cvt(Ab + (r0    ) * LDA + kh + tig * 2 + 8);
                af[mi][3] = ld2cvt(Ab + (r0 + 8) * LDA + kh + tig * 2 + 8);
            }
#pragma unroll
            for (int j = 0; j < 8; j++) {
                const int nr = wn + j * 8 + grp;
                uint32_t b0 = *(const uint32_t*)&Bb[nr * LDB + kh + tig * 2];
                uint32_t b1 = *(const uint32_t*)&Bb[nr * LDB + kh + tig * 2 + 8];
#pragma unroll
                for (int mi = 0; mi < 2; mi++)
                    mma16816(acc[mi][j], af[mi][0], af[mi][1], af[mi][2], af[mi][3], b0, b1);
            }
        }
        __syncthreads();
    }

#pragma unroll
    for (int mi = 0; mi < 2; mi++) {
#pragma unroll
        for (int j = 0; j < 8; j++) {
            const int col = ncol + wn + j * 8 + 2 * tig;
            const float bx = bias[col], by = bias[col + 1];
            const int r0 = brow + wm + mi * 16 + grp;
            const int r1 = r0 + 8;
            if (Ch) {
                if (r0 < M)
                    *(__half2*)(Ch + (size_t)r0 * N + col) =
                        __floats2half2_rn(acc[mi][j][0] + bx, acc[mi][j][1] + by);
                if (r1 < M)
                    *(__half2*)(Ch + (size_t)r1 * N + col) =
                        __floats2half2_rn(acc[mi][j][2] + bx, acc[mi][j][3] + by);
            } else {
                if (r0 < M)
                    *(float2*)(Cf + (size_t)r0 * N + col) =
                        make_float2(acc[mi][j][0] + bx, acc[mi][j][1] + by);
                if (r1 < M)
                    *(float2*)(Cf + (size_t)r1 * N + col) =
                        make_float2(acc[mi][j][2] + bx, acc[mi][j][3] + by);
            }
        }
    }
}

// ---- fused K1+K2: one launch; K2's latency-bound blocks scheduled first ----
#define K1_TX 532
#define K2_TX 63
#define K2_BLOCKS (K2_TX * 3)
#define K1_BLOCKS (K1_TX * 2)

__global__ __launch_bounds__(256, 2)
void gemm_fused(const float* __restrict__ value, const float* __restrict__ query,
                const float* __restrict__ b_v)
{
    const int bid = blockIdx.x;
    if (bid < K2_BLOCKS) {
        const int bx = bid % K2_TX, by = bid / K2_TX;
        gemm_body(query, g_wqT, g_bq, g_offattn, nullptr,
                  BS * LQ, 384, bx * 128, by * 128);
    } else {
        const int r = bid - K2_BLOCKS;
        const int bx = r % K1_TX, by = r / K1_TX;
        gemm_body(value, g_wvT, b_v, nullptr, g_vph,
                  BS * LV, 256, bx * 128, by * 128);
    }
}

// ---- K4 (fp16 A, full-K prefetch: all 8 stages issued up front) ------------
__global__ __launch_bounds__(256, 1)
void gemm_k4(const float* __restrict__ b_o, float* __restrict__ out)
{
    extern __shared__ __align__(16) char smem[];
    __half* As = (__half*)smem;                        // [8][STG_B]
    __half* Bs = (__half*)(smem + SMEM_K4_A);

    const int M = BS * LQ, N = 256;
    const int brow = blockIdx.x * 128;
    const int ncol = blockIdx.y * 128;

    const int tid  = threadIdx.x;
    const int wid  = tid >> 5;
    const int lane = tid & 31;
    const int wm   = (wid & 3) * 32;
    const int wn   = (wid >> 2) * 64;
    const int grp  = lane >> 2;
    const int tig  = lane & 3;

    float acc[2][8][4];
#pragma unroll
    for (int i = 0; i < 2; i++)
#pragma unroll
        for (int j = 0; j < 8; j++)
#pragma unroll
            for (int r = 0; r < 4; r++) acc[i][j][r] = 0.f;

    // issue ALL 8 stage loads up front (one commit group per stage)
#pragma unroll
    for (int s = 0; s < 8; s++) {
        const int kb = s * 32;
#pragma unroll
        for (int t = 0; t < 2; t++) {
            const int lin = tid + t * 256;
            const int row = lin >> 2;
            const int c   = lin & 3;
            const __half* sa = g_tmph + (size_t)min(brow + row, M - 1) * 256 + kb + c * 8;
            cpasync16((uint32_t)__cvta_generic_to_shared(&As[s * STG_B + row * LDB + c * 8]), sa);
            const __half* sb = g_woT + (size_t)(ncol + row) * 256 + kb + c * 8;
            cpasync16((uint32_t)__cvta_generic_to_shared(&Bs[s * STG_B + row * LDB + c * 8]), sb);
        }
        cp_commit();
    }

#pragma unroll
    for (int it = 0; it < 8; it++) {
        // wait until stages 0..it have landed (7-it groups may remain pending)
        if      (it == 0) cp_wait<7>();
        else if (it == 1) cp_wait<6>();
        else if (it == 2) cp_wait<5>();
        else if (it == 3) cp_wait<4>();
        else if (it == 4) cp_wait<3>();
        else if (it == 5) cp_wait<2>();
        else if (it == 6) cp_wait<1>();
        else              cp_wait<0>();
        __syncthreads();

        const __half* Ab = As + it * STG_B;
        const __half* Bb = Bs + it * STG_B;

#pragma unroll
        for (int ks = 0; ks < 2; ks++) {
            const int kh = ks * 16;
            uint32_t af[2][4];
#pragma unroll
            for (int mi = 0; mi < 2; mi++) {
                const int r0 = wm + mi * 16 + grp;
                af[mi][0] = *(const uint32_t*)&Ab[(r0    ) * LDB + kh + tig * 2];
                af[mi][1] = *(const uint32_t*)&Ab[(r0 + 8) * LDB + kh + tig * 2];
                af[mi][2] = *(const uint32_t*)&Ab[(r0    ) * LDB + kh + tig * 2 + 8];
                af[mi][3] = *(const uint32_t*)&Ab[(r0 + 8) * LDB + kh + tig * 2 + 8];
            }
#pragma unroll
            for (int j = 0; j < 8; j++) {
                const int nr = wn + j * 8 + grp;
                uint32_t b0 = *(const uint32_t*)&Bb[nr * LDB + kh + tig * 2];
                uint32_t b1 = *(const uint32_t*)&Bb[nr * LDB + kh + tig * 2 + 8];
#pragma unroll
                for (int mi = 0; mi < 2; mi++)
                    mma16816(acc[mi][j], af[mi][0], af[mi][1], af[mi][2], af[mi][3], b0, b1);
            }
        }
        // no syncthreads needed after compute: buffers are never rewritten
    }

#pragma unroll
    for (int mi = 0; mi < 2; mi++) {
#pragma unroll
        for (int j = 0; j < 8; j++) {
            const int col = ncol + wn + j * 8 + 2 * tig;
            const float bx = b_o[col], by = b_o[col + 1];
            const int r0 = brow + wm + mi * 16 + grp;
            const int r1 = r0 + 8;
            if (r0 < M)
                *(float2*)(out + (size_t)r0 * N + col) =
                    make_float2(acc[mi][j][0] + bx, acc[mi][j][1] + by);
            if (r1 < M)
                *(float2*)(out + (size_t)r1 * N + col) =
                    make_float2(acc[mi][j][2] + bx, acc[mi][j][3] + by);
        }
    }
}

// ========= fused transpose+convert of all weights + bias pack ==============
__global__ void transpose_all(const float* __restrict__ w_v,
                              const float* __restrict__ w_off,
                              const float* __restrict__ w_attn,
                              const float* __restrict__ w_o,
                              const float* __restrict__ b_off,
                              const float* __restrict__ b_attn)
{
    const int z = blockIdx.z;
    const int tid = threadIdx.y * 32 + threadIdx.x;
    if (z == 4) {
        if (blockIdx.x == 0 && blockIdx.y == 0) {
            if (tid < 256) g_bq[tid] = b_off[tid];
            if (tid < 128) g_bq[256 + tid] = b_attn[tid];
        }
        return;
    }
    const float* src = (z == 0) ? w_v : (z == 1) ? w_off : (z == 2) ? w_attn : w_o;
    __half* dst      = (z == 0) ? g_wvT : (z == 1) ? g_wqT : (z == 2) ? (g_wqT + 256 * DD) : g_woT;
    const int N = (z == 2) ? 128 : 256;
    if (blockIdx.x * 32 >= N) return;

    __shared__ float t[32][33];
    const int n0 = blockIdx.x * 32;
    const int k0 = blockIdx.y * 32;
    const int x = threadIdx.x, y = threadIdx.y;   // 32 x 8
#pragma unroll
    for (int i = 0; i < 32; i += 8)
        t[y + i][x] = src[(size_t)(k0 + y + i) * N + n0 + x];
    __syncthreads();
#pragma unroll
    for (int i = 0; i < 32; i += 8)
        dst[(size_t)(n0 + y + i) * 256 + k0 + x] = __float2half(t[x][y + i]);
}

// ---------------- fused softmax + bilinear sampling + aggregation ----------
// TWO queries per block; phase 1 fills all 256 threads; phase 2 interleaves
// both queries' gathers (8 independent loads in flight per iteration).
__global__ __launch_bounds__(256)
void sample_agg_kernel(const float* __restrict__ ref)
{
    __shared__ __align__(16) float2 swo[2][128][4];   // [q][point][corner]

    const int bq0 = blockIdx.x * 2;
    const int tid = threadIdx.x;

    const int Wl[NL] = {80, 40, 20, 10};
    const int St[NL] = {0, 6400, 8000, 8400};

    {
        const int q  = tid >> 7;
        const int t  = tid & 127;
        const int bq = bq0 + q;
        const int b  = bq / LQ;
        const int h  = t >> 4;
        const int i  = t & 15;
        const int l  = i >> 2;

        float logit = g_offattn[(size_t)bq * 384 + 256 + t];
        float m = logit;
#pragma unroll
        for (int d = 8; d; d >>= 1) m = fmaxf(m, __shfl_xor_sync(0xffffffffu, m, d, 16));
        float e = __expf(logit - m);
        float s = e;
#pragma unroll
        for (int d = 8; d; d >>= 1) s += __shfl_xor_sync(0xffffffffu, s, d, 16);
        const float aw = e / s;

        const float ox = g_offattn[(size_t)bq * 384 + 2 * t];
        const float oy = g_offattn[(size_t)bq * 384 + 2 * t + 1];
        const float rx = ref[((size_t)bq * NL + l) * 2 + 0];
        const float ry = ref[((size_t)bq * NL + l) * 2 + 1];

        const int   W = Wl[l], H = Wl[l];
        const float Wf = (float)W;

        const float x = fmaf(rx, Wf, ox) - 0.5f;
        const float y = fmaf(ry, Wf, oy) - 0.5f;
        const float x0f = floorf(x), y0f = floorf(y);
        const int   x0 = (int)x0f,  y0 = (int)y0f;
        const float fx = x - x0f,   fy = y - y0f;

        const float w00 = (1.f - fx) * (1.f - fy) * aw;
        const float w10 = fx * (1.f - fy) * aw;
        const float w01 = (1.f - fx) * fy * aw;
        const float w11 = fx * fy * aw;

        const bool vx0 = (x0 >= 0) && (x0 < W);
        const bool vx1 = (x0 + 1 >= 0) && (x0 + 1 < W);
        const bool vy0 = (y0 >= 0) && (y0 < H);
        const bool vy1 = (y0 + 1 >= 0) && (y0 + 1 < H);

        const int pbase = b * LV + St[l];
        const int hoff  = h * CC;

        const int i00 = ((pbase + y0 * W + x0) * DD + hoff) << 1;
        const int i10 = i00 + (DD << 1);
        const int i01 = i00 + (W * DD << 1);
        const int i11 = i01 + (DD << 1);

        swo[q][t][0] = make_float2((vx0 && vy0) ? w00 : 0.f, __int_as_float((vx0 && vy0) ? i00 : 0));
        swo[q][t][1] = make_float2((vx1 && vy0) ? w10 : 0.f, __int_as_float((vx1 && vy0) ? i10 : 0));
        swo[q][t][2] = make_float2((vx0 && vy1) ? w01 : 0.f, __int_as_float((vx0 && vy1) ? i01 : 0));
        swo[q][t][3] = make_float2((vx1 && vy1) ? w11 : 0.f, __int_as_float((vx1 && vy1) ? i11 : 0));
    }
    __syncthreads();

    const int h    = tid >> 5;
    const int lane = tid & 31;
    const int lh   = lane >> 4;
    const int ch   = (lane & 15) * 2;
    const char* base = (const char*)g_vph + (ch << 1);

    float ax0 = 0.f, ay0 = 0.f, ax1 = 0.f, ay1 = 0.f;
#pragma unroll
    for (int i = 0; i < 8; i++) {
        const int t = h * 16 + i * 2 + lh;
        float4 q0a = *(const float4*)(&swo[0][t][0]);
        float4 q0b = *(const float4*)(&swo[0][t][2]);
        float4 q1a = *(const float4*)(&swo[1][t][0]);
        float4 q1b = *(const float4*)(&swo[1][t][2]);
#pragma unroll
        for (int c = 0; c < 4; c++) {
            const float w0 = (c == 0) ? q0a.x : (c == 1) ? q0a.z : (c == 2) ? q0b.x : q0b.z;
            const float o0 = (c == 0) ? q0a.y : (c == 1) ? q0a.w : (c == 2) ? q0b.y : q0b.w;
            const float w1 = (c == 0) ? q1a.x : (c == 1) ? q1a.z : (c == 2) ? q1b.x : q1b.z;
            const float o1 = (c == 0) ? q1a.y : (c == 1) ? q1a.w : (c == 2) ? q1b.y : q1b.w;
            const __half2 v0 = *(const __half2*)(base + __float_as_int(o0));
            const __half2 v1 = *(const __half2*)(base + __float_as_int(o1));
            const float2 f0 = __half22float2(v0);
            const float2 f1 = __half22float2(v1);
            ax0 = fmaf(w0, f0.x, ax0);
            ay0 = fmaf(w0, f0.y, ay0);
            ax1 = fmaf(w1, f1.x, ax1);
            ay1 = fmaf(w1, f1.y, ay1);
        }
    }
    ax0 += __shfl_xor_sync(0xffffffffu, ax0, 16);
    ay0 += __shfl_xor_sync(0xffffffffu, ay0, 16);
    ax1 += __shfl_xor_sync(0xffffffffu, ax1, 16);
    ay1 += __shfl_xor_sync(0xffffffffu, ay1, 16);
    if (lh == 0) {
        *(__half2*)(g_tmph + (size_t)(bq0    ) * DD + h * CC + ch) = __floats2half2_rn(ax0, ay0);
        *(__half2*)(g_tmph + (size_t)(bq0 + 1) * DD + h * CC + ch) = __floats2half2_rn(ax1, ay1);
    }
}

// ---------------------------------------------------------------------------
extern "C" void kernel_launch(void* const* d_in, const int* in_sizes, int n_in,
                              void* d_out, int out_size)
{
    const float* query  = (const float*)d_in[0];
    const float* refpts = (const float*)d_in[1];
    const float* value  = (const float*)d_in[2];
    const float* w_off  = (const float*)d_in[3];
    const float* b_off  = (const float*)d_in[4];
    const float* w_attn = (const float*)d_in[5];
    const float* b_attn = (const float*)d_in[6];
    const float* w_v    = (const float*)d_in[7];
    const float* b_v    = (const float*)d_in[8];
    const float* w_o    = (const float*)d_in[9];
    const float* b_o    = (const float*)d_in[10];
    float* out = (float*)d_out;

    cudaFuncSetAttribute(gemm_fused, cudaFuncAttributeMaxDynamicSharedMemorySize, SMEM_GEMM);
    cudaFuncSetAttribute(gemm_k4,    cudaFuncAttributeMaxDynamicSharedMemorySize, SMEM_K4);

    // weight transposes + bias pack (one launch)
    transpose_all<<<dim3(8, 8, 5), dim3(32, 8)>>>(w_v, w_off, w_attn, w_o, b_off, b_attn);

    // K1 (value proj -> fp16 Vp) + K2 (query -> off|attn), fused single launch
    gemm_fused<<<K1_BLOCKS + K2_BLOCKS, 256, SMEM_GEMM>>>(value, query, b_v);

    // K3: softmax + sampling + aggregation -> fp16 (2 queries / block)
    sample_agg_kernel<<<BS * LQ / 2, 256>>>(refpts);

    // K4: out = tmph @ w_o + b_o -> fp32 (full-K prefetch)
    gemm_k4<<<dim3(K2_TX, 2), 256, SMEM_K4>>>(b_o, out);
}